// round 1
// baseline (speedup 1.0000x reference)
#include <cuda_runtime.h>

// Problem constants
#define BB 4
#define NN 1024
#define DD 768
#define HH 12
#define HD 64
#define BH 48            // BB*HH
#define KTH 104857       // int(1024*1024*0.1)

// ---------------- scratch (device globals; no allocations allowed) ----------
__device__ float g_qkv[4096 * 2304];            // [B*N, 3*D]  (3,H,hd per row)
__device__ float g_attn[(size_t)48 * 1024 * 1024]; // scores -> probs, [bh][n][m]
__device__ float g_ao[4096 * 768];              // attention output [B*N, D]
__device__ unsigned g_hist[48 * 2048];
__device__ unsigned g_prefix[48];
__device__ int g_krem[48];
__device__ float g_thr[48];

// monotone float->uint key (ascending)
__device__ __forceinline__ unsigned fkey(float f) {
    unsigned u = __float_as_uint(f);
    return (u & 0x80000000u) ? ~u : (u ^ 0x80000000u);
}

// ---------------------------------------------------------------------------
// Generic GEMM: C[M,N] = A[M,K] @ B[K,N] + bias[N]
// 128x128 block tile, BK=8, 256 threads, 8x8 per thread. All dims divide.
// ---------------------------------------------------------------------------
__global__ void gemm128_bias(const float* __restrict__ A, const float* __restrict__ Bm,
                             const float* __restrict__ bias, float* __restrict__ C,
                             int M, int Nn, int K) {
    __shared__ float As[8][128];
    __shared__ float Bs[8][128];
    int t = threadIdx.x;
    int n0 = blockIdx.x * 128;
    int m0 = blockIdx.y * 128;
    int tx = t & 15, ty = t >> 4;
    float acc[8][8];
#pragma unroll
    for (int i = 0; i < 8; i++)
#pragma unroll
        for (int j = 0; j < 8; j++) acc[i][j] = 0.f;

    int arow = t >> 1, acol = (t & 1) * 4;
    int brow = t >> 5, bcol = (t & 31) * 4;

    for (int k0 = 0; k0 < K; k0 += 8) {
        float4 av = *(const float4*)(A + (size_t)(m0 + arow) * K + k0 + acol);
        As[acol + 0][arow] = av.x;
        As[acol + 1][arow] = av.y;
        As[acol + 2][arow] = av.z;
        As[acol + 3][arow] = av.w;
        float4 bv = *(const float4*)(Bm + (size_t)(k0 + brow) * Nn + n0 + bcol);
        *(float4*)&Bs[brow][bcol] = bv;
        __syncthreads();
#pragma unroll
        for (int kk = 0; kk < 8; kk++) {
            float a[8], b[8];
#pragma unroll
            for (int i = 0; i < 8; i++) a[i] = As[kk][ty * 8 + i];
#pragma unroll
            for (int j = 0; j < 8; j++) b[j] = Bs[kk][tx * 8 + j];
#pragma unroll
            for (int i = 0; i < 8; i++)
#pragma unroll
                for (int j = 0; j < 8; j++) acc[i][j] += a[i] * b[j];
        }
        __syncthreads();
    }
    float bb[8];
#pragma unroll
    for (int j = 0; j < 8; j++) bb[j] = bias[n0 + tx * 8 + j];
#pragma unroll
    for (int i = 0; i < 8; i++) {
        int row = m0 + ty * 8 + i;
#pragma unroll
        for (int j0 = 0; j0 < 8; j0 += 4) {
            float4 v;
            v.x = acc[i][j0 + 0] + bb[j0 + 0];
            v.y = acc[i][j0 + 1] + bb[j0 + 1];
            v.z = acc[i][j0 + 2] + bb[j0 + 2];
            v.w = acc[i][j0 + 3] + bb[j0 + 3];
            *(float4*)(C + (size_t)row * Nn + n0 + tx * 8 + j0) = v;
        }
    }
}

// ---------------------------------------------------------------------------
// Scores: S[bh][n][m] = 0.125 * sum_d Q[n,d] K[m,d]
// ---------------------------------------------------------------------------
__global__ void gemm_scores() {
    int bh = blockIdx.z;
    int b = bh / HH, h = bh % HH;
    const float* Q = g_qkv + (size_t)b * NN * 2304 + h * HD;
    const float* Kp = g_qkv + (size_t)b * NN * 2304 + 768 + h * HD;
    float* S = g_attn + (size_t)bh * NN * NN;

    __shared__ float Qs[8][128];
    __shared__ float Ks[8][128];
    int t = threadIdx.x;
    int m0 = blockIdx.x * 128;   // key index
    int n0 = blockIdx.y * 128;   // query index
    int tx = t & 15, ty = t >> 4;
    float acc[8][8];
#pragma unroll
    for (int i = 0; i < 8; i++)
#pragma unroll
        for (int j = 0; j < 8; j++) acc[i][j] = 0.f;

    int r = t >> 1, c4 = (t & 1) * 4;

    for (int d0 = 0; d0 < HD; d0 += 8) {
        float4 qv = *(const float4*)(Q + (size_t)(n0 + r) * 2304 + d0 + c4);
        Qs[c4 + 0][r] = qv.x; Qs[c4 + 1][r] = qv.y;
        Qs[c4 + 2][r] = qv.z; Qs[c4 + 3][r] = qv.w;
        float4 kv = *(const float4*)(Kp + (size_t)(m0 + r) * 2304 + d0 + c4);
        Ks[c4 + 0][r] = kv.x; Ks[c4 + 1][r] = kv.y;
        Ks[c4 + 2][r] = kv.z; Ks[c4 + 3][r] = kv.w;
        __syncthreads();
#pragma unroll
        for (int kk = 0; kk < 8; kk++) {
            float a[8], bvv[8];
#pragma unroll
            for (int i = 0; i < 8; i++) a[i] = Qs[kk][ty * 8 + i];
#pragma unroll
            for (int j = 0; j < 8; j++) bvv[j] = Ks[kk][tx * 8 + j];
#pragma unroll
            for (int i = 0; i < 8; i++)
#pragma unroll
                for (int j = 0; j < 8; j++) acc[i][j] += a[i] * bvv[j];
        }
        __syncthreads();
    }
#pragma unroll
    for (int i = 0; i < 8; i++) {
        int row = n0 + ty * 8 + i;
#pragma unroll
        for (int j0 = 0; j0 < 8; j0 += 4) {
            float4 v;
            v.x = acc[i][j0 + 0] * 0.125f;
            v.y = acc[i][j0 + 1] * 0.125f;
            v.z = acc[i][j0 + 2] * 0.125f;
            v.w = acc[i][j0 + 3] * 0.125f;
            *(float4*)(S + (size_t)row * NN + m0 + tx * 8 + j0) = v;
        }
    }
}

// ---------------------------------------------------------------------------
// Radix select (exact kth smallest over 1M values per bh), 3 passes 11/11/10
// ---------------------------------------------------------------------------
__global__ void sel_init() {
    int bh = blockIdx.x;
    int t = threadIdx.x;
    for (int j = t; j < 2048; j += 256) g_hist[bh * 2048 + j] = 0u;
    if (t == 0) { g_krem[bh] = KTH; g_prefix[bh] = 0u; }
}

template <int PASS>
__global__ void hist_pass() {
    int bh = blockIdx.y;
    __shared__ unsigned sh[2048];
    int t = threadIdx.x;
    for (int j = t; j < 2048; j += 256) sh[j] = 0u;
    __syncthreads();
    unsigned pre = g_prefix[bh];
    const float* S = g_attn + (size_t)bh * 1048576 + (size_t)blockIdx.x * 16384;
#pragma unroll 4
    for (int i = 0; i < 64; i++) {
        unsigned key = fkey(S[i * 256 + t]);
        if (PASS == 0) {
            atomicAdd(&sh[key >> 21], 1u);
        } else if (PASS == 1) {
            if ((key >> 21) == pre) atomicAdd(&sh[(key >> 10) & 2047u], 1u);
        } else {
            if ((key >> 10) == pre) atomicAdd(&sh[key & 1023u], 1u);
        }
    }
    __syncthreads();
    for (int j = t; j < 2048; j += 256) {
        unsigned c = sh[j];
        if (c) atomicAdd(&g_hist[bh * 2048 + j], c);
    }
}

template <int PASS>
__global__ void scan_pass() {
    int bh = blockIdx.x;
    const int BINS = (PASS == 2) ? 1024 : 2048;
    const int PER = BINS / 256;
    int t = threadIdx.x;
    __shared__ unsigned ssum[256];
    __shared__ int s_sel;
    __shared__ unsigned s_kin;
    unsigned* hist = g_hist + bh * 2048;
    unsigned loc[8];
    unsigned lsum = 0;
#pragma unroll
    for (int i = 0; i < PER; i++) { loc[i] = hist[t * PER + i]; lsum += loc[i]; }
    ssum[t] = lsum;
    __syncthreads();
    if (t == 0) {
        unsigned k = (unsigned)g_krem[bh];
        unsigned cum = 0;
        int sel = 255;
        unsigned kin = k;
        for (int i = 0; i < 256; i++) {
            if (cum + ssum[i] >= k) { sel = i; kin = k - cum; break; }
            cum += ssum[i];
        }
        s_sel = sel; s_kin = kin;
    }
    __syncthreads();
    if (t == s_sel) {
        unsigned k = s_kin, cum = 0;
        int d = t * PER;
        unsigned knew = k;
#pragma unroll
        for (int i = 0; i < PER; i++) {
            if (cum + loc[i] >= k) { d = t * PER + i; knew = k - cum; break; }
            cum += loc[i];
        }
        g_krem[bh] = (int)knew;
        if (PASS == 0) {
            g_prefix[bh] = (unsigned)d;
        } else if (PASS == 1) {
            g_prefix[bh] = (g_prefix[bh] << 11) | (unsigned)d;
        } else {
            unsigned key = (g_prefix[bh] << 10) | (unsigned)d;
            unsigned bits = (key & 0x80000000u) ? (key ^ 0x80000000u) : ~key;
            g_thr[bh] = __uint_as_float(bits);
        }
    }
    __syncthreads();
    for (int j = t; j < 2048; j += 256) hist[j] = 0u;
}

// ---------------------------------------------------------------------------
// Masked softmax, one block per row (in place on g_attn)
// ---------------------------------------------------------------------------
__global__ void softmax_mask() {
    int row = blockIdx.x;
    int bh = row >> 10;
    float thr = g_thr[bh];
    float* S = g_attn + (size_t)row * NN;
    int t = threadIdx.x;
    unsigned lane = t & 31, w = t >> 5;
    __shared__ float red[8];

    float v[4];
    float mx = -3.0e38f;
#pragma unroll
    for (int i = 0; i < 4; i++) {
        float s = S[t + i * 256];
        v[i] = (s <= thr) ? -1e9f : s;
        mx = fmaxf(mx, v[i]);
    }
#pragma unroll
    for (int o = 16; o; o >>= 1) mx = fmaxf(mx, __shfl_xor_sync(0xffffffffu, mx, o));
    if (lane == 0) red[w] = mx;
    __syncthreads();
    float m = red[0];
#pragma unroll
    for (int i = 1; i < 8; i++) m = fmaxf(m, red[i]);

    float e[4];
    float s = 0.f;
#pragma unroll
    for (int i = 0; i < 4; i++) { e[i] = __expf(v[i] - m); s += e[i]; }
#pragma unroll
    for (int o = 16; o; o >>= 1) s += __shfl_xor_sync(0xffffffffu, s, o);
    __syncthreads();
    if (lane == 0) red[w] = s;
    __syncthreads();
    float tot = 0.f;
#pragma unroll
    for (int i = 0; i < 8; i++) tot += red[i];
    float inv = 1.f / tot;
#pragma unroll
    for (int i = 0; i < 4; i++) S[t + i * 256] = e[i] * inv;
}

// ---------------------------------------------------------------------------
// AV: O[b,n,h*64+j] = sum_m P[bh][n][m] V[b,m,h,j];  128(M) x 64(N) tile, BK=8
// ---------------------------------------------------------------------------
__global__ void gemm_av() {
    int bh = blockIdx.z;
    int b = bh / HH, h = bh % HH;
    const float* P = g_attn + (size_t)bh * NN * NN;
    const float* V = g_qkv + (size_t)b * NN * 2304 + 1536 + h * HD;
    float* O = g_ao + (size_t)b * NN * DD + h * HD;

    __shared__ float As[8][128];
    __shared__ float Bs[8][64];
    int t = threadIdx.x;
    int m0 = blockIdx.y * 128;   // query rows
    int tx = t & 15, ty = t >> 4;
    float acc[8][4];
#pragma unroll
    for (int i = 0; i < 8; i++)
#pragma unroll
        for (int j = 0; j < 4; j++) acc[i][j] = 0.f;

    int arow = t >> 1, acol = (t & 1) * 4;

    for (int k0 = 0; k0 < NN; k0 += 8) {
        float4 av = *(const float4*)(P + (size_t)(m0 + arow) * NN + k0 + acol);
        As[acol + 0][arow] = av.x;
        As[acol + 1][arow] = av.y;
        As[acol + 2][arow] = av.z;
        As[acol + 3][arow] = av.w;
        if (t < 128) {
            int brow = t >> 4, bcol = (t & 15) * 4;
            float4 bv = *(const float4*)(V + (size_t)(k0 + brow) * 2304 + bcol);
            *(float4*)&Bs[brow][bcol] = bv;
        }
        __syncthreads();
#pragma unroll
        for (int kk = 0; kk < 8; kk++) {
            float a[8], bvv[4];
#pragma unroll
            for (int i = 0; i < 8; i++) a[i] = As[kk][ty * 8 + i];
#pragma unroll
            for (int j = 0; j < 4; j++) bvv[j] = Bs[kk][tx * 4 + j];
#pragma unroll
            for (int i = 0; i < 8; i++)
#pragma unroll
                for (int j = 0; j < 4; j++) acc[i][j] += a[i] * bvv[j];
        }
        __syncthreads();
    }
#pragma unroll
    for (int i = 0; i < 8; i++) {
        int row = m0 + ty * 8 + i;
        float4 v;
        v.x = acc[i][0]; v.y = acc[i][1]; v.z = acc[i][2]; v.w = acc[i][3];
        *(float4*)(O + (size_t)row * DD + tx * 4) = v;
    }
}

// ---------------------------------------------------------------------------
extern "C" void kernel_launch(void* const* d_in, const int* in_sizes, int n_in,
                              void* d_out, int out_size) {
    const float* x = (const float*)d_in[0];
    const float* W_qkv = (const float*)d_in[1];
    const float* b_qkv = (const float*)d_in[2];
    const float* W_out = (const float*)d_in[3];
    const float* b_out = (const float*)d_in[4];
    float* out = (float*)d_out;

    float* qkv_p; cudaGetSymbolAddress((void**)&qkv_p, g_qkv);
    float* ao_p;  cudaGetSymbolAddress((void**)&ao_p, g_ao);

    // 1. QKV projection: [4096,768] @ [768,2304] + bias
    gemm128_bias<<<dim3(2304 / 128, 4096 / 128), 256>>>(x, W_qkv, b_qkv, qkv_p,
                                                        4096, 2304, 768);
    // 2. Scores
    gemm_scores<<<dim3(8, 8, BH), 256>>>();
    // 3. Exact kth-smallest threshold per (b,h)
    sel_init<<<BH, 256>>>();
    hist_pass<0><<<dim3(64, BH), 256>>>();
    scan_pass<0><<<BH, 256>>>();
    hist_pass<1><<<dim3(64, BH), 256>>>();
    scan_pass<1><<<BH, 256>>>();
    hist_pass<2><<<dim3(64, BH), 256>>>();
    scan_pass<2><<<BH, 256>>>();
    // 4. Masked softmax in place
    softmax_mask<<<BH * NN, 256>>>();
    // 5. P @ V
    gemm_av<<<dim3(1, 8, BH), 256>>>();
    // 6. Output projection: [4096,768] @ [768,768] + bias
    gemm128_bias<<<dim3(768 / 128, 4096 / 128), 256>>>(ao_p, W_out, b_out, out,
                                                       4096, 768, 768);
}